// round 17
// baseline (speedup 1.0000x reference)
#include <cuda_runtime.h>
#include <cuda_fp16.h>
#include <math.h>

#define B 64
#define T 256
#define D 512
#define G4 2048
#define M_ROWS (B * T)   // 16384
#define DIN2 1024

typedef unsigned long long ull;

// ---------------- f32x2 helpers (input GEMM kernel) ----------------
__device__ __forceinline__ void fma2(ull &d, ull a, ull b) {
    asm("fma.rn.f32x2 %0, %1, %2, %0;" : "+l"(d) : "l"(a), "l"(b));
}
__device__ __forceinline__ ull dup2(float v) {
    ull r; unsigned u = __float_as_uint(v);
    asm("mov.b64 %0, {%1, %1};" : "=l"(r) : "r"(u));
    return r;
}
__device__ __forceinline__ float2 unpk(ull v) {
    float2 f;
    asm("mov.b64 {%0, %1}, %2;" : "=f"(f.x), "=f"(f.y) : "l"(v));
    return f;
}

// ---------------- release/acquire barrier primitives ----------------
__device__ __forceinline__ void red_release_add(unsigned* p, unsigned v) {
    asm volatile("red.release.gpu.global.add.u32 [%0], %1;"
                 :: "l"(p), "r"(v) : "memory");
}
__device__ __forceinline__ unsigned atom_acqrel_add(unsigned* p, unsigned v) {
    unsigned old;
    asm volatile("atom.acq_rel.gpu.global.add.u32 %0, [%1], %2;"
                 : "=r"(old) : "l"(p), "r"(v) : "memory");
    return old;
}
__device__ __forceinline__ void st_release(unsigned* p, unsigned v) {
    asm volatile("st.release.gpu.global.u32 [%0], %1;"
                 :: "l"(p), "r"(v) : "memory");
}
__device__ __forceinline__ unsigned ld_acquire(const unsigned* p) {
    unsigned v;
    asm volatile("ld.acquire.gpu.global.u32 %0, [%1];"
                 : "=r"(v) : "l"(p) : "memory");
    return v;
}

// ---------------- warp-MMA primitives (standard PTX; HMMA on sm_103) ----------
__device__ __forceinline__ void ldsm_x4(unsigned* r, unsigned addr) {
    asm volatile("ldmatrix.sync.aligned.m8n8.x4.shared.b16 {%0,%1,%2,%3}, [%4];"
        : "=r"(r[0]), "=r"(r[1]), "=r"(r[2]), "=r"(r[3]) : "r"(addr));
}
__device__ __forceinline__ void ldsm_x2(unsigned* r, unsigned addr) {
    asm volatile("ldmatrix.sync.aligned.m8n8.x2.shared.b16 {%0,%1}, [%2];"
        : "=r"(r[0]), "=r"(r[1]) : "r"(addr));
}
__device__ __forceinline__ void mma16816(float* c, const unsigned* a, const unsigned* b) {
    asm volatile(
        "mma.sync.aligned.m16n8k16.row.col.f32.f16.f16.f32 "
        "{%0,%1,%2,%3}, {%4,%5,%6,%7}, {%8,%9}, {%0,%1,%2,%3};"
        : "+f"(c[0]), "+f"(c[1]), "+f"(c[2]), "+f"(c[3])
        : "r"(a[0]), "r"(a[1]), "r"(a[2]), "r"(a[3]), "r"(b[0]), "r"(b[1]));
}

// ---------------- device scratch ----------------
__device__ float g_xz_f[(size_t)M_ROWS * G4];
__device__ float g_xz_b[(size_t)M_ROWS * G4];
__device__ float g_y1[(size_t)M_ROWS * DIN2];
// pre-split h halves: [which(hi=0,lo=1)][ping][dir][B*D] f16
__device__ __half g_hs[2][2][2][B * D];
__device__ float g_hfin[2 * B * D];
__device__ float g_c[2 * B * D];
__device__ unsigned char g_mask[M_ROWS];
__device__ unsigned g_cta_arr[2][64][32];   // [dir][cta][pad]
__device__ unsigned g_cnt[2][32];           // [dir][pad]
__device__ unsigned g_gen[2][32];           // [dir][pad] release generation word

// ---------------- fused: mask + zero split h + barrier reset ----------------
__global__ void maskinit_kernel(const float* __restrict__ X) {
    int tid = threadIdx.x;
    int gidx = blockIdx.x * 128 + tid;
    if (gidx < 2 * 2 * 2 * B * D / 2) ((unsigned*)g_hs)[gidx] = 0u;
    if (gidx < 2 * 64 * 32) ((unsigned*)g_cta_arr)[gidx] = 0u;
    if (gidx < 2 * 32) ((unsigned*)g_cnt)[gidx] = 0u;
    if (gidx < 2 * 32) ((unsigned*)g_gen)[gidx] = 0u;
    int row = blockIdx.x * 4 + (tid >> 5);
    int lane = tid & 31;
    const float* p = X + (size_t)row * D;
    int any = 0;
    for (int k = lane; k < D; k += 32) any |= (p[k] != 0.0f);
    any = __any_sync(0xffffffffu, any);
    if (lane == 0) g_mask[row] = (unsigned char)any;
}

// ---------------- FFMA2 GEMM: C[M,2048] = A[M,K] @ W[K,2048] + bias ----------
__global__ void __launch_bounds__(256, 2) gemm_bias_kernel(
    const float* __restrict__ Aext, int a_is_y1,
    const float* __restrict__ W, const float* __restrict__ bias,
    int c_sel, int K)
{
    const float* A = a_is_y1 ? g_y1 : Aext;
    float* C = c_sel ? g_xz_b : g_xz_f;

    __shared__ float As[2][16 * 128];
    __shared__ float Bs[2][16 * 128];

    int tid = threadIdx.x;
    int m0 = blockIdx.y << 7, n0 = blockIdx.x << 7;
    int warp = tid >> 5, lane = tid & 31;
    int wm = (warp & 3) << 5, wn = (warp >> 2) << 6;
    int lm = (lane >> 3) << 2, ln = (lane & 7) << 2;
    int am = tid & 127, akg = tid >> 7;
    int bn4 = tid & 31, bk0 = tid >> 5;

    ull acc[8][4];
#pragma unroll
    for (int r = 0; r < 8; r++)
#pragma unroll
        for (int s = 0; s < 4; s++) acc[r][s] = 0ULL;

    float4 aR[2], bR[2];
    const size_t arow = (size_t)(m0 + am) * K;

#define LDG_TILE(k0)                                                          \
    aR[0] = *(const float4*)&A[arow + (k0) + (akg << 2)];                     \
    aR[1] = *(const float4*)&A[arow + (k0) + ((akg + 2) << 2)];               \
    bR[0] = *(const float4*)&W[(size_t)((k0) + bk0) * G4 + n0 + (bn4 << 2)];  \
    bR[1] = *(const float4*)&W[(size_t)((k0) + bk0 + 8) * G4 + n0 + (bn4 << 2)];

#define STS_TILE(buf)                                                         \
    {                                                                         \
        float* Ad = As[buf]; float* Bd = Bs[buf];                             \
        Ad[((akg << 2) + 0) * 128 + am] = aR[0].x;                            \
        Ad[((akg << 2) + 1) * 128 + am] = aR[0].y;                            \
        Ad[((akg << 2) + 2) * 128 + am] = aR[0].z;                            \
        Ad[((akg << 2) + 3) * 128 + am] = aR[0].w;                            \
        Ad[(((akg + 2) << 2) + 0) * 128 + am] = aR[1].x;                      \
        Ad[(((akg + 2) << 2) + 1) * 128 + am] = aR[1].y;                      \
        Ad[(((akg + 2) << 2) + 2) * 128 + am] = aR[1].z;                      \
        Ad[(((akg + 2) << 2) + 3) * 128 + am] = aR[1].w;                      \
        *(float4*)&Bd[bk0 * 128 + (bn4 << 2)] = bR[0];                        \
        *(float4*)&Bd[(bk0 + 8) * 128 + (bn4 << 2)] = bR[1];                  \
    }

    LDG_TILE(0);
    STS_TILE(0);
    __syncthreads();

    int KT = K >> 4;
    for (int kt = 0; kt < KT; kt++) {
        int cur = kt & 1;
        if (kt + 1 < KT) { LDG_TILE((kt + 1) << 4); }
        const float* Ab = As[cur];
        const float* Bb = Bs[cur];
#pragma unroll
        for (int kk = 0; kk < 16; kk++) {
            float4 a0 = *(const float4*)&Ab[kk * 128 + wm + lm];
            float4 a1 = *(const float4*)&Ab[kk * 128 + wm + lm + 16];
            ulonglong2 b0 = *(const ulonglong2*)&Bb[kk * 128 + wn + ln];
            ulonglong2 b1 = *(const ulonglong2*)&Bb[kk * 128 + wn + ln + 32];
            ull ap[8];
            ap[0] = dup2(a0.x); ap[1] = dup2(a0.y); ap[2] = dup2(a0.z); ap[3] = dup2(a0.w);
            ap[4] = dup2(a1.x); ap[5] = dup2(a1.y); ap[6] = dup2(a1.z); ap[7] = dup2(a1.w);
#pragma unroll
            for (int r = 0; r < 8; r++) {
                fma2(acc[r][0], ap[r], b0.x);
                fma2(acc[r][1], ap[r], b0.y);
                fma2(acc[r][2], ap[r], b1.x);
                fma2(acc[r][3], ap[r], b1.y);
            }
        }
        if (kt + 1 < KT) {
            STS_TILE(cur ^ 1);
            __syncthreads();
        }
    }

    float4 bias0 = *(const float4*)&bias[n0 + wn + ln];
    float4 bias1 = *(const float4*)&bias[n0 + wn + ln + 32];
#pragma unroll
    for (int r = 0; r < 8; r++) {
        int mrow = m0 + wm + lm + (r < 4 ? r : 12 + r);
        float2 p0 = unpk(acc[r][0]), p1 = unpk(acc[r][1]);
        float2 p2 = unpk(acc[r][2]), p3 = unpk(acc[r][3]);
        float4 v0 = {p0.x + bias0.x, p0.y + bias0.y, p1.x + bias0.z, p1.y + bias0.w};
        float4 v1 = {p2.x + bias1.x, p2.y + bias1.y, p3.x + bias1.z, p3.y + bias1.w};
        size_t crow = (size_t)mrow * G4 + n0 + wn + ln;
        *(float4*)&C[crow] = v0;
        *(float4*)&C[crow + 32] = v1;
    }
#undef LDG_TILE
#undef STS_TILE
}

// ---------------- persistent scan: transposed warp-MMA, U fragments in regs ---
// zT[32 units][64 batches] = U_sliceT[32,512] @ hT[512,64].
// 16 warps = 2 m-groups x 8 k-slabs (64 k each). A(U) frags cached in registers
// once; per-step smem traffic is h(B-side) only. zpT[8][32][72] aliases h tile.
#define HSTRIDE_B 1040
#define OFF_HHI  0
#define OFF_HLO  (64 * HSTRIDE_B)
#define OFF_UHI  (2 * 64 * HSTRIDE_B)
#define OFF_ULO  (OFF_UHI + 32 * HSTRIDE_B)
#define OFF_MASK (OFF_ULO + 32 * HSTRIDE_B)
#define SMEM_SCAN (OFF_MASK + 16384)

__global__ void __launch_bounds__(512) lstm_scan_kernel(
    const float* __restrict__ Uf, const float* __restrict__ Ub,
    float* dout, int out_is_y1)
{
    extern __shared__ char smb[];
    unsigned smem_base;
    asm("{ .reg .u64 t; cvta.to.shared.u64 t, %1; cvt.u32.u64 %0, t; }"
        : "=r"(smem_base) : "l"(smb));
    unsigned char* mask_s = (unsigned char*)(smb + OFF_MASK);
    float* zp = (float*)(smb + OFF_HHI);   // 8 x [32][72] f32, aliases h tiles

    int tid = threadIdx.x;
    int lane = tid & 31, wid = tid >> 5;
    int dir = blockIdx.x >> 6;
    int cta = blockIdx.x & 63;
    int u0 = cta << 3;

    const float* U = dir ? Ub : Uf;
    const float* xz = dir ? g_xz_b : g_xz_f;
    float* outb = (out_is_y1 ? g_y1 : dout) + dir * D;
    unsigned* my_arr = &g_cta_arr[dir][cta][0];
    unsigned* my_cnt = &g_cnt[dir][0];
    unsigned* my_gen = &g_gen[dir][0];

    // ---- stage U slice ONCE as hi/lo f16, [n=32 units][k=512] row-major ----
    for (int i = tid; i < 32 * 512; i += 512) {
        int n = i & 31, k = i >> 5;
        int col = ((n >> 3) << 9) + u0 + (n & 7);
        float v = U[(size_t)k * G4 + col];
        __half hv = __float2half_rn(v);
        __half lv = __float2half_rn(v - __half2float(hv));
        *(__half*)(smb + OFF_UHI + n * HSTRIDE_B + (k << 1)) = hv;
        *(__half*)(smb + OFF_ULO + n * HSTRIDE_B + (k << 1)) = lv;
    }
    {
        const int4* msrc = (const int4*)g_mask;
        int4* mdst = (int4*)mask_s;
        for (int i = tid; i < M_ROWS / 16; i += 512) mdst[i] = msrc[i];
    }
    __syncthreads();

    // thread roles
    int b = tid >> 3, u = tid & 7;            // gate-phase element (b, unit)
    int cb = u0 + u;
    int mg = wid & 1, ks = wid >> 1;          // 2 m-groups x 8 k-slabs

    // ---- load U(A-side) fragments ONCE into registers ----
    unsigned ua_hi = smem_base + OFF_UHI + ((mg << 4) + (lane & 15)) * HSTRIDE_B
                     + ((lane >> 4) << 4);
    unsigned ua_lo = ua_hi + (OFF_ULO - OFF_UHI);
    unsigned ufhi[4][4], uflo[4][4];
#pragma unroll
    for (int kc = 0; kc < 4; kc++) {
        unsigned kbyte = (unsigned)(((ks << 6) + (kc << 4)) << 1);
        ldsm_x4(ufhi[kc], ua_hi + kbyte);
        ldsm_x4(uflo[kc], ua_lo + kbyte);
    }

    // B(h) base address (R12-verified ldsm pattern; rows = batches)
    unsigned b_base = smem_base + OFF_HHI + (lane & 7) * HSTRIDE_B
                      + (((lane >> 3) & 1) << 4);

    float c_reg = 0.f, h_reg = 0.f, po_reg = 0.f;

    for (int s = 0; s < T; s++) {
        int ping = s & 1;
        int t_d = dir ? (T - 1 - s) : s;
        const __half* hs_hi = &g_hs[0][ping][dir][0];
        const __half* hs_lo = &g_hs[1][ping][dir][0];
        __half* hd_hi = &g_hs[0][ping ^ 1][dir][0];
        __half* hd_lo = &g_hs[1][ping ^ 1][dir][0];

        // ---- prefetch xz (long latency, issued first) + mask ----
        int row = b * T + t_d;
        size_t xr = (size_t)row * G4;
        float xz0 = __ldcg(&xz[xr + cb]);
        float xz1 = __ldcg(&xz[xr + 512 + cb]);
        float xz2 = __ldcg(&xz[xr + 1024 + cb]);
        float xz3 = __ldcg(&xz[xr + 1536 + cb]);
        unsigned mrv = mask_s[row];

        // ---- stage h: pure uint4 copy of pre-split hi/lo tiles ----
#pragma unroll
        for (int it = 0; it < 8; it++) {
            int idx = tid + (it << 9);        // 0..4095
            int hb = idx >> 6, ck = idx & 63;
            uint4 vh = __ldcg((const uint4*)(hs_hi + (hb << 9)) + ck);
            uint4 vl = __ldcg((const uint4*)(hs_lo + (hb << 9)) + ck);
            unsigned o = hb * HSTRIDE_B + (ck << 4);
            *(uint4*)(smb + OFF_HHI + o) = vh;
            *(uint4*)(smb + OFF_HLO + o) = vl;
        }
        __syncthreads();

        // ---- zT partial = U(regs) @ h(smem) over this slab's 64 k ----
        float acc[8][4];
#pragma unroll
        for (int nt = 0; nt < 8; nt++)
#pragma unroll
            for (int i = 0; i < 4; i++) acc[nt][i] = 0.f;

#pragma unroll
        for (int kc = 0; kc < 4; kc++) {
            unsigned kbyte = (unsigned)(((ks << 6) + (kc << 4)) << 1);
#pragma unroll
            for (int nt = 0; nt < 8; nt++) {
                unsigned baddr = b_base + (unsigned)(nt << 3) * HSTRIDE_B + kbyte;
                unsigned bhi[2], blo[2];
                ldsm_x2(bhi, baddr);
                ldsm_x2(blo, baddr + (OFF_HLO - OFF_HHI));
                mma16816(acc[nt], ufhi[kc], bhi);
                mma16816(acc[nt], ufhi[kc], blo);
                mma16816(acc[nt], uflo[kc], bhi);
            }
        }
        __syncthreads();   // all h-tile reads done; zp aliasing now safe

        // ---- write k-slab partials: zpT[ks][unit 32][batch 72] ----
        {
            float* myzp = zp + ks * (32 * 72);
            int r = (mg << 4) + (lane >> 2), c2 = (lane & 3) << 1;
#pragma unroll
            for (int nt = 0; nt < 8; nt++) {
                int col = (nt << 3) + c2;
                myzp[r * 72 + col]           = acc[nt][0];
                myzp[r * 72 + col + 1]       = acc[nt][1];
                myzp[(r + 8) * 72 + col]     = acc[nt][2];
                myzp[(r + 8) * 72 + col + 1] = acc[nt][3];
            }
        }
        __syncthreads();

        // ---- gates + state update (1 element per thread) ----
        {
            float zi = xz0, zf = xz1, zg = xz2, zo = xz3;
#pragma unroll
            for (int p = 0; p < 8; p++) {
                const float* zb = zp + p * (32 * 72);
                zi += zb[u * 72 + b];
                zf += zb[(8 + u) * 72 + b];
                zg += zb[(16 + u) * 72 + b];
                zo += zb[(24 + u) * 72 + b];
            }
            float iv = 1.0f / (1.0f + expf(-zi));
            float fv = 1.0f / (1.0f + expf(-zf));
            float gv = tanhf(zg);
            float ov = 1.0f / (1.0f + expf(-zo));
            float c_new = fv * c_reg + iv * gv;
            float h_new = ov * tanhf(c_new);
            bool m = mrv != 0u;
            c_reg  = m ? c_new : c_reg;
            h_reg  = m ? h_new : h_reg;
            po_reg = m ? h_new : po_reg;
            __half hh = __float2half_rn(h_reg);
            __half hl = __float2half_rn(h_reg - __half2float(hh));
            hd_hi[(b << 9) + cb] = hh;
            hd_lo[(b << 9) + cb] = hl;
        }

        bool not_last = (s + 1 < T);
        if (not_last) {
            // every thread: release-arrive (orders own h stores first)
            red_release_add(my_arr, 1u);
        }

        // ---- per-timestep output write (overlaps barrier) ----
        outb[(size_t)row * 1024 + cb] = po_reg;

        if (not_last) {
            if (tid == 0) {
                unsigned tgt_cta = 512u * (unsigned)(s + 1);
                while (ld_acquire(my_arr) < tgt_cta) {}     // single reader: raw spin
                unsigned old = atom_acqrel_add(my_cnt, 1u);
                unsigned g = (unsigned)(s + 1);
                if (old == 64u * g - 1u) {
                    st_release(my_gen, g);                  // winner releases everyone
                } else {
                    while (ld_acquire(my_gen) < g) {}       // poll write-once word
                }
            }
            __syncthreads();
        }
    }

    g_hfin[dir * (B * D) + b * D + cb] = h_reg;
    g_c[dir * (B * D) + b * D + cb] = c_reg;
}

// ---------------- final hidden/cell concat ----------------
__global__ void finalize_kernel(float* dout, int out_size) {
    int i = blockIdx.x * blockDim.x + threadIdx.x;
    if (i >= B * 2 * D) return;
    size_t hoff = (size_t)B * T * 1024;
    if ((size_t)out_size < hoff + 2 * (size_t)(B * 2 * D)) return;
    int b = i >> 10, j = i & 1023;
    int dir = j >> 9, u = j & 511;
    int sidx = dir * (B * D) + b * D + u;
    dout[hoff + i] = g_hfin[sidx];
    dout[hoff + B * 2 * D + i] = g_c[sidx];
}

// ---------------- host orchestration ----------------
extern "C" void kernel_launch(void* const* d_in, const int* in_sizes, int n_in,
                              void* d_out, int out_size) {
    const float* X   = (const float*)d_in[0];
    const float* Wf1 = (const float*)d_in[1];
    const float* Uf1 = (const float*)d_in[2];
    const float* bf1 = (const float*)d_in[3];
    const float* Wb1 = (const float*)d_in[4];
    const float* Ub1 = (const float*)d_in[5];
    const float* bb1 = (const float*)d_in[6];
    const float* Wf2 = (const float*)d_in[7];
    const float* Uf2 = (const float*)d_in[8];
    const float* bf2 = (const float*)d_in[9];
    const float* Wb2 = (const float*)d_in[10];
    const float* Ub2 = (const float*)d_in[11];
    const float* bb2 = (const float*)d_in[12];
    float* out = (float*)d_out;

    cudaFuncSetAttribute(lstm_scan_kernel,
                         cudaFuncAttributeMaxDynamicSharedMemorySize, SMEM_SCAN);

    dim3 ggrid(G4 / 128, M_ROWS / 128);

    // launch order puts scans at positions 4 and 8 (ncu capture slots)
    maskinit_kernel<<<M_ROWS / 4, 128>>>(X);                       // 1
    gemm_bias_kernel<<<ggrid, 256>>>(X, 0, Wf1, bf1, 0, 512);      // 2
    gemm_bias_kernel<<<ggrid, 256>>>(X, 0, Wb1, bb1, 1, 512);      // 3
    lstm_scan_kernel<<<128, 512, SMEM_SCAN>>>(Uf1, Ub1, out, 1);   // 4

    gemm_bias_kernel<<<ggrid, 256>>>(nullptr, 1, Wf2, bf2, 0, 1024); // 5
    gemm_bias_kernel<<<ggrid, 256>>>(nullptr, 1, Wb2, bb2, 1, 1024); // 6
    maskinit_kernel<<<M_ROWS / 4, 128>>>(X);                         // 7
    lstm_scan_kernel<<<128, 512, SMEM_SCAN>>>(Uf2, Ub2, out, 0);     // 8

    finalize_kernel<<<256, 256>>>(out, out_size);                    // 9
}